// round 12
// baseline (speedup 1.0000x reference)
#include <cuda_runtime.h>
#include <cstdint>

// Flash attention, tf32 mma.sync (m16n8k8), fp32 accumulate.
// B=16, Q=2048, K=2048, D=128. Per-batch key masking via valid_lens.
// Round 12: R8 pipeline with BKT=32 so smem/CTA = 73,728B (exactly 9
// granules) and regs fit 85/thread -> 3 CTAs/SM = 24 warps in 3
// independent barrier domains. No-max softmax. Persistent atomic queue.

static constexpr int BQ   = 64;
static constexpr int BKT  = 32;
static constexpr int HD   = 128;
static constexpr int SEQ  = 2048;
static constexpr int NB   = 16;
static constexpr int NITEMS = (SEQ / BQ) * NB;   // 512

// smem float offsets
static constexpr int Q_OFF = 0;        // 64x128 = 8192 floats
static constexpr int K_OFF = 8192;     // 32x128 = 4096
static constexpr int V_OFF = 12288;    // 32x128 = 4096
static constexpr int P_OFF = 16384;    // 64x32  = 2048 (XOR-swizzled; also scratch)
static constexpr int SMEM_FLOATS = P_OFF + 2048;   // 18432 -> 73728 B = 9 granules

__device__ int g_ctr;
__global__ void reset_ctr_kernel() { g_ctr = 0; }

__device__ __forceinline__ unsigned f2tf(float x) {
    unsigned r;
    asm("cvt.rna.tf32.f32 %0, %1;" : "=r"(r) : "f"(x));
    return r;
}

__device__ __forceinline__ void mma8(float* c,
                                     unsigned a0, unsigned a1, unsigned a2, unsigned a3,
                                     unsigned b0, unsigned b1) {
    asm volatile(
        "mma.sync.aligned.m16n8k8.row.col.f32.tf32.tf32.f32 "
        "{%0,%1,%2,%3}, {%4,%5,%6,%7}, {%8,%9}, {%0,%1,%2,%3};\n"
        : "+f"(c[0]), "+f"(c[1]), "+f"(c[2]), "+f"(c[3])
        : "r"(a0), "r"(a1), "r"(a2), "r"(a3), "r"(b0), "r"(b1));
}

__device__ __forceinline__ void cpa16(uint32_t dst, const void* src) {
    asm volatile("cp.async.cg.shared.global [%0], [%1], 16;\n" :: "r"(dst), "l"(src));
}

extern __shared__ float smem[];

__global__ __launch_bounds__(256, 3)
void fa_tf32_kernel(const float* __restrict__ q,
                    const float* __restrict__ k,
                    const float* __restrict__ v,
                    const int*   __restrict__ vlens,
                    float*       __restrict__ out) {
    const int tid  = threadIdx.x;
    const int warp = tid >> 5;
    const int lane = tid & 31;
    const int g    = lane >> 2;
    const int t    = lane & 3;
    const int wq   = warp >> 1;        // 16-row q block (0..3)
    const int h    = warp & 1;         // key-half (S) / d-half (PV)

    const float scale = 0.088388347648318447f;  // 1/sqrt(128)

    uint32_t smem_u32;
    asm("{ .reg .u64 tmp; cvta.to.shared.u64 tmp, %1; cvt.u32.u64 %0, tmp; }"
        : "=r"(smem_u32) : "l"(smem));

    const uint32_t kK_base = smem_u32 + (uint32_t)K_OFF * 4u;
    const uint32_t kV_base = smem_u32 + (uint32_t)V_OFF * 4u;

    const float* sQ = smem + Q_OFF;
    float*       sP = smem + P_OFF;
    float*       sSum = smem + P_OFF;                        // epilogue scratch
    int*         sItem = reinterpret_cast<int*>(smem + P_OFF + 130);

    const int row0 = wq * 16 + g;      // row0 & 7 == g
    const int row1 = row0 + 8;

    while (true) {
        __syncthreads();     // previous item fully done
        if (tid == 0) *sItem = atomicAdd(&g_ctr, 1);
        __syncthreads();
        const int item = *sItem;
        if (item >= NITEMS) return;

        const int b  = item & (NB - 1);
        const int q0 = (item >> 4) * BQ;
        const int vlen = vlens[b];
        const int nkt  = (vlen + BKT - 1) >> 5;

        const float4* gQ4 = reinterpret_cast<const float4*>(q + ((size_t)b * SEQ + q0) * HD);
        const float4* gK4 = reinterpret_cast<const float4*>(k + (size_t)b * SEQ * HD);
        const float4* gV4 = reinterpret_cast<const float4*>(v + (size_t)b * SEQ * HD);

        // ---- prologue: issue K(0), V(0) loads (32 rows x 32 float4 each) ----
        #pragma unroll
        for (int i = 0; i < 4; i++) {
            int idx = tid + i * 256;       // 0..1023 float4
            int row = idx >> 5;            // 0..31
            int c4  = idx & 31;
            int dK = row * 32 + (c4 ^ (row & 7));
            int dV = row * 32 + (c4 ^ ((row & 7) << 1));
            cpa16(kK_base + (uint32_t)dK * 16u, gK4 + idx);
            cpa16(kV_base + (uint32_t)dV * 16u, gV4 + idx);
        }
        asm volatile("cp.async.commit_group;\n" ::: "memory");

        // ---- Q tile: scale + tf32 into swizzled smem (overlaps cp.async) ----
        {
            float* sQw = smem + Q_OFF;
            #pragma unroll
            for (int i = 0; i < 8; i++) {
                int idx = tid + i * 256;   // 0..2047 float4
                int row = idx >> 5;
                int c4  = idx & 31;
                float4 x = gQ4[idx];
                x.x = __uint_as_float(f2tf(x.x * scale));
                x.y = __uint_as_float(f2tf(x.y * scale));
                x.z = __uint_as_float(f2tf(x.z * scale));
                x.w = __uint_as_float(f2tf(x.w * scale));
                int d4 = row * 32 + (c4 ^ (row & 7));
                *reinterpret_cast<float4*>(&sQw[d4 * 4]) = x;
            }
        }

        float lacc0 = 0.f, lacc1 = 0.f;
        float oAcc[8][4];
        #pragma unroll
        for (int n = 0; n < 8; n++)
            #pragma unroll
            for (int e = 0; e < 4; e++) oAcc[n][e] = 0.f;

        for (int kt = 0; kt < nkt; kt++) {
            const int kbase = kt * BKT;

            asm volatile("cp.async.wait_group 0;\n" ::: "memory");
            __syncthreads();

            const float* sK = smem + K_OFF;
            const float* sV = smem + V_OFF;

            // ---- in-smem tf32 convert: K + V (8192 floats contiguous) ----
            #pragma unroll
            for (int i = 0; i < 8; i++) {
                float4* p = reinterpret_cast<float4*>(smem + K_OFF) + (tid + i * 256);
                float4 x = *p;
                x.x = __uint_as_float(f2tf(x.x));
                x.y = __uint_as_float(f2tf(x.y));
                x.z = __uint_as_float(f2tf(x.z));
                x.w = __uint_as_float(f2tf(x.w));
                *p = x;
            }
            __syncthreads();

            // ---- S = Q @ K^T : 16 rows x 16 keys (half h) per warp ----
            float sAcc[2][4];
            #pragma unroll
            for (int n = 0; n < 2; n++)
                #pragma unroll
                for (int e = 0; e < 4; e++) sAcc[n][e] = 0.f;

            const int krow = h * 16;
            #pragma unroll
            for (int s = 0; s < 16; s++) {
                const int cA0 = ((2 * s)     ^ g) * 4 + t;
                const int cA1 = ((2 * s + 1) ^ g) * 4 + t;
                unsigned a0 = __float_as_uint(sQ[row0 * 128 + cA0]);
                unsigned a1 = __float_as_uint(sQ[row1 * 128 + cA0]);
                unsigned a2 = __float_as_uint(sQ[row0 * 128 + cA1]);
                unsigned a3 = __float_as_uint(sQ[row1 * 128 + cA1]);
                #pragma unroll
                for (int n = 0; n < 2; n++) {
                    unsigned b0 = __float_as_uint(sK[(krow + n * 8 + g) * 128 + cA0]);
                    unsigned b1 = __float_as_uint(sK[(krow + n * 8 + g) * 128 + cA1]);
                    mma8(sAcc[n], a0, a1, a2, a3, b0, b1);
                }
            }

            // ---- exp (no max), mask, swizzled P store, row-sum partials ----
            const bool boundary = (kbase + BKT > vlen);
            const int sub = (t & 1) * 2;
            #pragma unroll
            for (int n = 0; n < 2; n++) {
                float p0 = __expf(sAcc[n][0]);
                float p1 = __expf(sAcc[n][1]);
                float p2 = __expf(sAcc[n][2]);
                float p3 = __expf(sAcc[n][3]);
                if (boundary) {
                    int key = kbase + h * 16 + n * 8 + 2 * t;
                    if (key     >= vlen) { p0 = 0.f; p2 = 0.f; }
                    if (key + 1 >= vlen) { p1 = 0.f; p3 = 0.f; }
                }
                lacc0 += p0 + p1;
                lacc1 += p2 + p3;
                int c4p = h * 4 + 2 * n + (t >> 1);          // col>>2 (0..7)
                int idx0 = row0 * 32 + ((c4p ^ g) << 2) + sub;
                int idx1 = row1 * 32 + ((c4p ^ g) << 2) + sub;
                *reinterpret_cast<float2*>(&sP[idx0]) = make_float2(p0, p1);
                *reinterpret_cast<float2*>(&sP[idx1]) = make_float2(p2, p3);
            }

            __syncthreads();   // P ready; K buffer no longer needed

            // ---- overlap: prefetch K(kt+1) during PV ----
            if (kt + 1 < nkt) {
                int koff = (kt + 1) * BKT * 32;
                #pragma unroll
                for (int i = 0; i < 4; i++) {
                    int idx = tid + i * 256;
                    int row = idx >> 5;
                    int c4  = idx & 31;
                    int dK = row * 32 + (c4 ^ (row & 7));
                    cpa16(kK_base + (uint32_t)dK * 16u, gK4 + koff + idx);
                }
                asm volatile("cp.async.commit_group;\n" ::: "memory");
            }

            // ---- O += P @ V : 16 rows x 64 d-cols (half h) per warp ----
            const int u = g >> 2;
            const int w = g & 3;
            #pragma unroll
            for (int s = 0; s < 4; s++) {
                unsigned a0 = __float_as_uint(sP[row0 * 32 + (((2 * s)     ^ g) << 2) + t]);
                unsigned a1 = __float_as_uint(sP[row1 * 32 + (((2 * s)     ^ g) << 2) + t]);
                unsigned a2 = __float_as_uint(sP[row0 * 32 + (((2 * s + 1) ^ g) << 2) + t]);
                unsigned a3 = __float_as_uint(sP[row1 * 32 + (((2 * s + 1) ^ g) << 2) + t]);
                const int r0 = (s * 8 + t) * 128;           // rows 0..31, row&7 == t
                const int r1 = (s * 8 + t + 4) * 128;       // row&7 == t+4
                #pragma unroll
                for (int n = 0; n < 8; n++) {
                    int c4a = (16 * h + 2 * n + u) ^ (2 * t);
                    int c4b = (16 * h + 2 * n + u) ^ (2 * t + 8);
                    unsigned b0 = __float_as_uint(sV[r0 + c4a * 4 + w]);
                    unsigned b1 = __float_as_uint(sV[r1 + c4b * 4 + w]);
                    mma8(oAcc[n], a0, a1, a2, a3, b0, b1);
                }
            }

            __syncthreads();   // V buffer free (all PV readers done)

            // ---- issue V(kt+1) load ----
            if (kt + 1 < nkt) {
                int koff = (kt + 1) * BKT * 32;
                #pragma unroll
                for (int i = 0; i < 4; i++) {
                    int idx = tid + i * 256;
                    int row = idx >> 5;
                    int c4  = idx & 31;
                    int dV = row * 32 + (c4 ^ ((row & 7) << 1));
                    cpa16(kV_base + (uint32_t)dV * 16u, gV4 + koff + idx);
                }
                asm volatile("cp.async.commit_group;\n" ::: "memory");
            }
        }

        // ---- epilogue: cross-half row-sum exchange, normalize, store ----
        float rs0 = lacc0, rs1 = lacc1;
        rs0 += __shfl_xor_sync(0xffffffffu, rs0, 1);
        rs0 += __shfl_xor_sync(0xffffffffu, rs0, 2);
        rs1 += __shfl_xor_sync(0xffffffffu, rs1, 1);
        rs1 += __shfl_xor_sync(0xffffffffu, rs1, 2);
        __syncthreads();      // P (scratch region) free
        if (t == 0) {
            sSum[h * 64 + row0] = rs0;
            sSum[h * 64 + row1] = rs1;
        }
        __syncthreads();
        float inv0 = 1.f / (sSum[row0] + sSum[64 + row0]);
        float inv1 = 1.f / (sSum[row1] + sSum[64 + row1]);

        float* gO = out + ((size_t)b * SEQ + q0) * HD;
        #pragma unroll
        for (int n = 0; n < 8; n++) {
            int col = h * 64 + n * 8 + 2 * t;
            *reinterpret_cast<float2*>(&gO[row0 * HD + col]) =
                make_float2(oAcc[n][0] * inv0, oAcc[n][1] * inv0);
            *reinterpret_cast<float2*>(&gO[row1 * HD + col]) =
                make_float2(oAcc[n][2] * inv1, oAcc[n][3] * inv1);
        }
    }
}

extern "C" void kernel_launch(void* const* d_in, const int* in_sizes, int n_in,
                              void* d_out, int out_size) {
    const float* q  = (const float*)d_in[0];
    const float* k  = (const float*)d_in[1];
    const float* v  = (const float*)d_in[2];
    const int*   vl = (const int*)d_in[3];
    float* out = (float*)d_out;

    size_t smem_bytes = (size_t)SMEM_FLOATS * sizeof(float);   // 73728
    cudaFuncSetAttribute(fa_tf32_kernel, cudaFuncAttributeMaxDynamicSharedMemorySize, (int)smem_bytes);

    reset_ctr_kernel<<<1, 1>>>();
    fa_tf32_kernel<<<444, 256, smem_bytes>>>(q, k, v, vl, out);
}

// round 13
// speedup vs baseline: 2.0500x; 2.0500x over previous
#include <cuda_runtime.h>
#include <cstdint>

// Flash attention, tf32 mma.sync (m16n8k8), fp32 accumulate.
// B=16, Q=2048, K=2048, D=128. Per-batch key masking via valid_lens.
// Round 13: exact R8 base (best: 208.9us) + LPT scheduling (batches sorted
// by descending vlen in a 1-thread prologue; longest work dispatched first,
// shortest last -> short straggler tail) + 2 redundant barriers removed.
// 2 CTAs/SM (smem 114688B = 14 granules), no-max softmax, swizzled P.

static constexpr int BQ   = 64;
static constexpr int BKT  = 64;
static constexpr int HD   = 128;
static constexpr int SEQ  = 2048;
static constexpr int NB   = 16;
static constexpr int NITEMS = (SEQ / BQ) * NB;   // 512

// smem float offsets
static constexpr int Q_OFF = 0;        // 64x128 = 8192 floats
static constexpr int K_OFF = 8192;     // 64x128 = 8192
static constexpr int V_OFF = 16384;    // 64x128 = 8192
static constexpr int P_OFF = 24576;    // 64x64  = 4096 (XOR-swizzled; also scratch)
static constexpr int SMEM_FLOATS = P_OFF + 4096;   // 28672 -> 114688 B

__device__ int g_ctr;
__device__ int g_perm[NB];

// 1-thread scheduler: reset queue, sort batches by descending vlen (LPT).
__global__ void sched_kernel(const int* __restrict__ vlens) {
    g_ctr = 0;
    int vl[NB];
    bool used[NB];
    #pragma unroll
    for (int i = 0; i < NB; i++) { vl[i] = vlens[i]; used[i] = false; }
    for (int r = 0; r < NB; r++) {
        int best = -1, bi = 0;
        for (int i = 0; i < NB; i++)
            if (!used[i] && vl[i] > best) { best = vl[i]; bi = i; }
        used[bi] = true;
        g_perm[r] = bi;
    }
}

__device__ __forceinline__ unsigned f2tf(float x) {
    unsigned r;
    asm("cvt.rna.tf32.f32 %0, %1;" : "=r"(r) : "f"(x));
    return r;
}

__device__ __forceinline__ void mma8(float* c,
                                     unsigned a0, unsigned a1, unsigned a2, unsigned a3,
                                     unsigned b0, unsigned b1) {
    asm volatile(
        "mma.sync.aligned.m16n8k8.row.col.f32.tf32.tf32.f32 "
        "{%0,%1,%2,%3}, {%4,%5,%6,%7}, {%8,%9}, {%0,%1,%2,%3};\n"
        : "+f"(c[0]), "+f"(c[1]), "+f"(c[2]), "+f"(c[3])
        : "r"(a0), "r"(a1), "r"(a2), "r"(a3), "r"(b0), "r"(b1));
}

__device__ __forceinline__ void cpa16(uint32_t dst, const void* src) {
    asm volatile("cp.async.cg.shared.global [%0], [%1], 16;\n" :: "r"(dst), "l"(src));
}

extern __shared__ float smem[];

__global__ __launch_bounds__(256, 2)
void fa_tf32_kernel(const float* __restrict__ q,
                    const float* __restrict__ k,
                    const float* __restrict__ v,
                    const int*   __restrict__ vlens,
                    float*       __restrict__ out) {
    const int tid  = threadIdx.x;
    const int warp = tid >> 5;
    const int lane = tid & 31;
    const int g    = lane >> 2;
    const int t    = lane & 3;
    const int wq   = warp >> 1;        // 16-row q block (0..3)
    const int h    = warp & 1;         // key-half (S) / d-half (PV)

    const float scale = 0.088388347648318447f;  // 1/sqrt(128)

    uint32_t smem_u32;
    asm("{ .reg .u64 tmp; cvta.to.shared.u64 tmp, %1; cvt.u32.u64 %0, tmp; }"
        : "=r"(smem_u32) : "l"(smem));

    const uint32_t kK_base = smem_u32 + (uint32_t)K_OFF * 4u;
    const uint32_t kV_base = smem_u32 + (uint32_t)V_OFF * 4u;

    const float* sQ = smem + Q_OFF;
    float*       sP = smem + P_OFF;
    float*       sSum = smem + P_OFF;                        // epilogue scratch
    int*         sItem = reinterpret_cast<int*>(smem + P_OFF + 130);

    const int row0 = wq * 16 + g;
    const int row1 = row0 + 8;

    while (true) {
        // NOTE: no leading barrier needed — every path to here passed the
        // epilogue's post-sSum barrier or this is the first iteration.
        if (tid == 0) *sItem = atomicAdd(&g_ctr, 1);
        __syncthreads();
        const int item = *sItem;
        if (item >= NITEMS) return;

        const int b  = g_perm[item >> 5];      // LPT: longest batches first
        const int q0 = (item & 31) * BQ;
        const int vlen = vlens[b];
        const int nkt  = (vlen + BKT - 1) >> 6;

        const float4* gQ4 = reinterpret_cast<const float4*>(q + ((size_t)b * SEQ + q0) * HD);
        const float4* gK4 = reinterpret_cast<const float4*>(k + (size_t)b * SEQ * HD);
        const float4* gV4 = reinterpret_cast<const float4*>(v + (size_t)b * SEQ * HD);

        // ---- prologue: issue K(0), V(0) loads ----
        #pragma unroll
        for (int i = 0; i < 8; i++) {
            int idx = tid + i * 256;       // 0..2047 float4
            int row = idx >> 5;
            int c4  = idx & 31;
            int dK = row * 32 + (c4 ^ (row & 7));
            int dV = row * 32 + (c4 ^ ((row & 7) << 1));
            cpa16(kK_base + (uint32_t)dK * 16u, gK4 + idx);
            cpa16(kV_base + (uint32_t)dV * 16u, gV4 + idx);
        }
        asm volatile("cp.async.commit_group;\n" ::: "memory");

        // ---- Q tile: scale + tf32 into swizzled smem (overlaps cp.async) ----
        {
            float* sQw = smem + Q_OFF;
            #pragma unroll
            for (int i = 0; i < 8; i++) {
                int idx = tid + i * 256;   // 0..2047 float4
                int row = idx >> 5;
                int c4  = idx & 31;
                float4 x = gQ4[idx];
                x.x = __uint_as_float(f2tf(x.x * scale));
                x.y = __uint_as_float(f2tf(x.y * scale));
                x.z = __uint_as_float(f2tf(x.z * scale));
                x.w = __uint_as_float(f2tf(x.w * scale));
                int d4 = row * 32 + (c4 ^ (row & 7));
                *reinterpret_cast<float4*>(&sQw[d4 * 4]) = x;
            }
        }

        float lacc0 = 0.f, lacc1 = 0.f;
        float oAcc[8][4];
        #pragma unroll
        for (int n = 0; n < 8; n++)
            #pragma unroll
            for (int e = 0; e < 4; e++) oAcc[n][e] = 0.f;

        for (int kt = 0; kt < nkt; kt++) {
            const int kbase = kt * BKT;

            asm volatile("cp.async.wait_group 0;\n" ::: "memory");
            __syncthreads();

            const float* sK = smem + K_OFF;
            const float* sV = smem + V_OFF;

            // ---- in-smem tf32 convert: K + V (16384 floats) ----
            #pragma unroll
            for (int i = 0; i < 16; i++) {
                float4* p = reinterpret_cast<float4*>(smem + K_OFF) + (tid + i * 256);
                float4 x = *p;
                x.x = __uint_as_float(f2tf(x.x));
                x.y = __uint_as_float(f2tf(x.y));
                x.z = __uint_as_float(f2tf(x.z));
                x.w = __uint_as_float(f2tf(x.w));
                *p = x;
            }
            __syncthreads();

            // ---- S = Q @ K^T : 16 rows x 32 keys (half h) per warp ----
            float sAcc[4][4];
            #pragma unroll
            for (int n = 0; n < 4; n++)
                #pragma unroll
                for (int e = 0; e < 4; e++) sAcc[n][e] = 0.f;

            const int krow = h * 32;
            #pragma unroll
            for (int s = 0; s < 16; s++) {
                const int cA0 = ((2 * s)     ^ g) * 4 + t;
                const int cA1 = ((2 * s + 1) ^ g) * 4 + t;
                unsigned a0 = __float_as_uint(sQ[row0 * 128 + cA0]);
                unsigned a1 = __float_as_uint(sQ[row1 * 128 + cA0]);
                unsigned a2 = __float_as_uint(sQ[row0 * 128 + cA1]);
                unsigned a3 = __float_as_uint(sQ[row1 * 128 + cA1]);
                #pragma unroll
                for (int n = 0; n < 4; n++) {
                    unsigned b0 = __float_as_uint(sK[(krow + n * 8 + g) * 128 + cA0]);
                    unsigned b1 = __float_as_uint(sK[(krow + n * 8 + g) * 128 + cA1]);
                    mma8(sAcc[n], a0, a1, a2, a3, b0, b1);
                }
            }

            // ---- exp (no max), mask, swizzled P store, row-sum partials ----
            const bool boundary = (kbase + BKT > vlen);
            const int sub = (t & 1) * 2;
            #pragma unroll
            for (int n = 0; n < 4; n++) {
                float p0 = __expf(sAcc[n][0]);
                float p1 = __expf(sAcc[n][1]);
                float p2 = __expf(sAcc[n][2]);
                float p3 = __expf(sAcc[n][3]);
                if (boundary) {
                    int key = kbase + h * 32 + n * 8 + 2 * t;
                    if (key     >= vlen) { p0 = 0.f; p2 = 0.f; }
                    if (key + 1 >= vlen) { p1 = 0.f; p3 = 0.f; }
                }
                lacc0 += p0 + p1;
                lacc1 += p2 + p3;
                int c4p = h * 8 + 2 * n + (t >> 1);          // col>>2
                int idx0 = row0 * 64 + ((c4p ^ g) << 2) + sub;
                int idx1 = row1 * 64 + ((c4p ^ g) << 2) + sub;
                *reinterpret_cast<float2*>(&sP[idx0]) = make_float2(p0, p1);
                *reinterpret_cast<float2*>(&sP[idx1]) = make_float2(p2, p3);
            }

            __syncthreads();   // P ready; K buffer no longer needed

            // ---- overlap: prefetch K(kt+1) during PV ----
            if (kt + 1 < nkt) {
                int koff = (kt + 1) * BKT * 32;
                #pragma unroll
                for (int i = 0; i < 8; i++) {
                    int idx = tid + i * 256;
                    int row = idx >> 5;
                    int c4  = idx & 31;
                    int dK = row * 32 + (c4 ^ (row & 7));
                    cpa16(kK_base + (uint32_t)dK * 16u, gK4 + koff + idx);
                }
                asm volatile("cp.async.commit_group;\n" ::: "memory");
            }

            // ---- O += P @ V : 16 rows x 64 d-cols (half h) per warp ----
            const int u = g >> 2;
            const int w = g & 3;
            #pragma unroll
            for (int s = 0; s < 8; s++) {
                unsigned a0 = __float_as_uint(sP[row0 * 64 + (((2 * s)     ^ g) << 2) + t]);
                unsigned a1 = __float_as_uint(sP[row1 * 64 + (((2 * s)     ^ g) << 2) + t]);
                unsigned a2 = __float_as_uint(sP[row0 * 64 + (((2 * s + 1) ^ g) << 2) + t]);
                unsigned a3 = __float_as_uint(sP[row1 * 64 + (((2 * s + 1) ^ g) << 2) + t]);
                const int r0 = (s * 8 + t) * 128;
                const int r1 = (s * 8 + t + 4) * 128;
                #pragma unroll
                for (int n = 0; n < 8; n++) {
                    int c4a = (16 * h + 2 * n + u) ^ (2 * t);
                    int c4b = (16 * h + 2 * n + u) ^ (2 * t + 8);
                    unsigned b0 = __float_as_uint(sV[r0 + c4a * 4 + w]);
                    unsigned b1 = __float_as_uint(sV[r1 + c4b * 4 + w]);
                    mma8(oAcc[n], a0, a1, a2, a3, b0, b1);
                }
            }

            __syncthreads();   // V buffer free; also covers P reads (PV done)

            // ---- issue V(kt+1) load ----
            if (kt + 1 < nkt) {
                int koff = (kt + 1) * BKT * 32;
                #pragma unroll
                for (int i = 0; i < 8; i++) {
                    int idx = tid + i * 256;
                    int row = idx >> 5;
                    int c4  = idx & 31;
                    int dV = row * 32 + (c4 ^ ((row & 7) << 1));
                    cpa16(kV_base + (uint32_t)dV * 16u, gV4 + koff + idx);
                }
                asm volatile("cp.async.commit_group;\n" ::: "memory");
            }
        }

        // ---- epilogue: cross-half row-sum exchange, normalize, store ----
        // (loop-end barrier already separates PV's P-reads from sSum writes)
        float rs0 = lacc0, rs1 = lacc1;
        rs0 += __shfl_xor_sync(0xffffffffu, rs0, 1);
        rs0 += __shfl_xor_sync(0xffffffffu, rs0, 2);
        rs1 += __shfl_xor_sync(0xffffffffu, rs1, 1);
        rs1 += __shfl_xor_sync(0xffffffffu, rs1, 2);
        if (t == 0) {
            sSum[h * 64 + row0] = rs0;
            sSum[h * 64 + row1] = rs1;
        }
        __syncthreads();
        float inv0 = 1.f / (sSum[row0] + sSum[64 + row0]);
        float inv1 = 1.f / (sSum[row1] + sSum[64 + row1]);

        float* gO = out + ((size_t)b * SEQ + q0) * HD;
        #pragma unroll
        for (int n = 0; n < 8; n++) {
            int col = h * 64 + n * 8 + 2 * t;
            *reinterpret_cast<float2*>(&gO[row0 * HD + col]) =
                make_float2(oAcc[n][0] * inv0, oAcc[n][1] * inv0);
            *reinterpret_cast<float2*>(&gO[row1 * HD + col]) =
                make_float2(oAcc[n][2] * inv1, oAcc[n][3] * inv1);
        }
        __syncthreads();   // sSum reads done before next item's sItem write/Q store
    }
}

extern "C" void kernel_launch(void* const* d_in, const int* in_sizes, int n_in,
                              void* d_out, int out_size) {
    const float* q  = (const float*)d_in[0];
    const float* k  = (const float*)d_in[1];
    const float* v  = (const float*)d_in[2];
    const int*   vl = (const int*)d_in[3];
    float* out = (float*)d_out;

    size_t smem_bytes = (size_t)SMEM_FLOATS * sizeof(float);   // 114688
    cudaFuncSetAttribute(fa_tf32_kernel, cudaFuncAttributeMaxDynamicSharedMemorySize, (int)smem_bytes);

    sched_kernel<<<1, 1>>>(vl);
    fa_tf32_kernel<<<304, 256, smem_bytes>>>(q, k, v, vl, out);
}

// round 14
// speedup vs baseline: 2.0794x; 1.0143x over previous
#include <cuda_runtime.h>
#include <cstdint>

// Flash attention, tf32 mma.sync (m16n8k8), fp32 accumulate.
// B=16, Q=2048, K=2048, D=128. Per-batch key masking via valid_lens.
// Round 14: R13 (156.1us) minus the in-smem K/V convert pass — cvt.rna
// applied per-use on K/V B-fragment loads (bit-identical results, -128KB
// crossbar bytes and -1 barrier per tile). LPT scheduling, 2 CTAs/SM,
// no-max softmax, swizzled P, K(kt+1) load overlaps PV.

static constexpr int BQ   = 64;
static constexpr int BKT  = 64;
static constexpr int HD   = 128;
static constexpr int SEQ  = 2048;
static constexpr int NB   = 16;
static constexpr int NITEMS = (SEQ / BQ) * NB;   // 512

// smem float offsets
static constexpr int Q_OFF = 0;        // 64x128 = 8192 floats
static constexpr int K_OFF = 8192;     // 64x128 = 8192
static constexpr int V_OFF = 16384;    // 64x128 = 8192
static constexpr int P_OFF = 24576;    // 64x64  = 4096 (XOR-swizzled; also scratch)
static constexpr int SMEM_FLOATS = P_OFF + 4096;   // 28672 -> 114688 B

__device__ int g_ctr;
__device__ int g_perm[NB];

// 1-thread scheduler: reset queue, sort batches by descending vlen (LPT).
__global__ void sched_kernel(const int* __restrict__ vlens) {
    g_ctr = 0;
    int vl[NB];
    bool used[NB];
    #pragma unroll
    for (int i = 0; i < NB; i++) { vl[i] = vlens[i]; used[i] = false; }
    for (int r = 0; r < NB; r++) {
        int best = -1, bi = 0;
        for (int i = 0; i < NB; i++)
            if (!used[i] && vl[i] > best) { best = vl[i]; bi = i; }
        used[bi] = true;
        g_perm[r] = bi;
    }
}

__device__ __forceinline__ unsigned f2tf(float x) {
    unsigned r;
    asm("cvt.rna.tf32.f32 %0, %1;" : "=r"(r) : "f"(x));
    return r;
}

__device__ __forceinline__ void mma8(float* c,
                                     unsigned a0, unsigned a1, unsigned a2, unsigned a3,
                                     unsigned b0, unsigned b1) {
    asm volatile(
        "mma.sync.aligned.m16n8k8.row.col.f32.tf32.tf32.f32 "
        "{%0,%1,%2,%3}, {%4,%5,%6,%7}, {%8,%9}, {%0,%1,%2,%3};\n"
        : "+f"(c[0]), "+f"(c[1]), "+f"(c[2]), "+f"(c[3])
        : "r"(a0), "r"(a1), "r"(a2), "r"(a3), "r"(b0), "r"(b1));
}

__device__ __forceinline__ void cpa16(uint32_t dst, const void* src) {
    asm volatile("cp.async.cg.shared.global [%0], [%1], 16;\n" :: "r"(dst), "l"(src));
}

extern __shared__ float smem[];

__global__ __launch_bounds__(256, 2)
void fa_tf32_kernel(const float* __restrict__ q,
                    const float* __restrict__ k,
                    const float* __restrict__ v,
                    const int*   __restrict__ vlens,
                    float*       __restrict__ out) {
    const int tid  = threadIdx.x;
    const int warp = tid >> 5;
    const int lane = tid & 31;
    const int g    = lane >> 2;
    const int t    = lane & 3;
    const int wq   = warp >> 1;        // 16-row q block (0..3)
    const int h    = warp & 1;         // key-half (S) / d-half (PV)

    const float scale = 0.088388347648318447f;  // 1/sqrt(128)

    uint32_t smem_u32;
    asm("{ .reg .u64 tmp; cvta.to.shared.u64 tmp, %1; cvt.u32.u64 %0, tmp; }"
        : "=r"(smem_u32) : "l"(smem));

    const uint32_t kK_base = smem_u32 + (uint32_t)K_OFF * 4u;
    const uint32_t kV_base = smem_u32 + (uint32_t)V_OFF * 4u;

    const float* sQ = smem + Q_OFF;
    float*       sP = smem + P_OFF;
    float*       sSum = smem + P_OFF;                        // epilogue scratch
    int*         sItem = reinterpret_cast<int*>(smem + P_OFF + 130);

    const int row0 = wq * 16 + g;
    const int row1 = row0 + 8;

    while (true) {
        if (tid == 0) *sItem = atomicAdd(&g_ctr, 1);
        __syncthreads();
        const int item = *sItem;
        if (item >= NITEMS) return;

        const int b  = g_perm[item >> 5];      // LPT: longest batches first
        const int q0 = (item & 31) * BQ;
        const int vlen = vlens[b];
        const int nkt  = (vlen + BKT - 1) >> 6;

        const float4* gQ4 = reinterpret_cast<const float4*>(q + ((size_t)b * SEQ + q0) * HD);
        const float4* gK4 = reinterpret_cast<const float4*>(k + (size_t)b * SEQ * HD);
        const float4* gV4 = reinterpret_cast<const float4*>(v + (size_t)b * SEQ * HD);

        // ---- prologue: issue K(0), V(0) loads ----
        #pragma unroll
        for (int i = 0; i < 8; i++) {
            int idx = tid + i * 256;       // 0..2047 float4
            int row = idx >> 5;
            int c4  = idx & 31;
            int dK = row * 32 + (c4 ^ (row & 7));
            int dV = row * 32 + (c4 ^ ((row & 7) << 1));
            cpa16(kK_base + (uint32_t)dK * 16u, gK4 + idx);
            cpa16(kV_base + (uint32_t)dV * 16u, gV4 + idx);
        }
        asm volatile("cp.async.commit_group;\n" ::: "memory");

        // ---- Q tile: scale + tf32 into swizzled smem (overlaps cp.async) ----
        {
            float* sQw = smem + Q_OFF;
            #pragma unroll
            for (int i = 0; i < 8; i++) {
                int idx = tid + i * 256;   // 0..2047 float4
                int row = idx >> 5;
                int c4  = idx & 31;
                float4 x = gQ4[idx];
                x.x = __uint_as_float(f2tf(x.x * scale));
                x.y = __uint_as_float(f2tf(x.y * scale));
                x.z = __uint_as_float(f2tf(x.z * scale));
                x.w = __uint_as_float(f2tf(x.w * scale));
                int d4 = row * 32 + (c4 ^ (row & 7));
                *reinterpret_cast<float4*>(&sQw[d4 * 4]) = x;
            }
        }

        float lacc0 = 0.f, lacc1 = 0.f;
        float oAcc[8][4];
        #pragma unroll
        for (int n = 0; n < 8; n++)
            #pragma unroll
            for (int e = 0; e < 4; e++) oAcc[n][e] = 0.f;

        for (int kt = 0; kt < nkt; kt++) {
            const int kbase = kt * BKT;

            asm volatile("cp.async.wait_group 0;\n" ::: "memory");
            __syncthreads();

            const float* sK = smem + K_OFF;
            const float* sV = smem + V_OFF;

            // ---- S = Q @ K^T : 16 rows x 32 keys (half h) per warp ----
            // K converted per-use (cvt.rna in regs, bit-identical to pass)
            float sAcc[4][4];
            #pragma unroll
            for (int n = 0; n < 4; n++)
                #pragma unroll
                for (int e = 0; e < 4; e++) sAcc[n][e] = 0.f;

            const int krow = h * 32;
            #pragma unroll
            for (int s = 0; s < 16; s++) {
                const int cA0 = ((2 * s)     ^ g) * 4 + t;
                const int cA1 = ((2 * s + 1) ^ g) * 4 + t;
                unsigned a0 = __float_as_uint(sQ[row0 * 128 + cA0]);
                unsigned a1 = __float_as_uint(sQ[row1 * 128 + cA0]);
                unsigned a2 = __float_as_uint(sQ[row0 * 128 + cA1]);
                unsigned a3 = __float_as_uint(sQ[row1 * 128 + cA1]);
                #pragma unroll
                for (int n = 0; n < 4; n++) {
                    unsigned b0 = f2tf(sK[(krow + n * 8 + g) * 128 + cA0]);
                    unsigned b1 = f2tf(sK[(krow + n * 8 + g) * 128 + cA1]);
                    mma8(sAcc[n], a0, a1, a2, a3, b0, b1);
                }
            }

            // ---- exp (no max), mask, swizzled P store, row-sum partials ----
            const bool boundary = (kbase + BKT > vlen);
            const int sub = (t & 1) * 2;
            #pragma unroll
            for (int n = 0; n < 4; n++) {
                float p0 = __expf(sAcc[n][0]);
                float p1 = __expf(sAcc[n][1]);
                float p2 = __expf(sAcc[n][2]);
                float p3 = __expf(sAcc[n][3]);
                if (boundary) {
                    int key = kbase + h * 32 + n * 8 + 2 * t;
                    if (key     >= vlen) { p0 = 0.f; p2 = 0.f; }
                    if (key + 1 >= vlen) { p1 = 0.f; p3 = 0.f; }
                }
                lacc0 += p0 + p1;
                lacc1 += p2 + p3;
                int c4p = h * 8 + 2 * n + (t >> 1);          // col>>2
                int idx0 = row0 * 64 + ((c4p ^ g) << 2) + sub;
                int idx1 = row1 * 64 + ((c4p ^ g) << 2) + sub;
                *reinterpret_cast<float2*>(&sP[idx0]) = make_float2(p0, p1);
                *reinterpret_cast<float2*>(&sP[idx1]) = make_float2(p2, p3);
            }

            __syncthreads();   // P ready; K buffer no longer needed

            // ---- overlap: prefetch K(kt+1) during PV ----
            if (kt + 1 < nkt) {
                int koff = (kt + 1) * BKT * 32;
                #pragma unroll
                for (int i = 0; i < 8; i++) {
                    int idx = tid + i * 256;
                    int row = idx >> 5;
                    int c4  = idx & 31;
                    int dK = row * 32 + (c4 ^ (row & 7));
                    cpa16(kK_base + (uint32_t)dK * 16u, gK4 + koff + idx);
                }
                asm volatile("cp.async.commit_group;\n" ::: "memory");
            }

            // ---- O += P @ V : 16 rows x 64 d-cols (half h) per warp ----
            // V converted per-use
            const int u = g >> 2;
            const int w = g & 3;
            #pragma unroll
            for (int s = 0; s < 8; s++) {
                unsigned a0 = __float_as_uint(sP[row0 * 64 + (((2 * s)     ^ g) << 2) + t]);
                unsigned a1 = __float_as_uint(sP[row1 * 64 + (((2 * s)     ^ g) << 2) + t]);
                unsigned a2 = __float_as_uint(sP[row0 * 64 + (((2 * s + 1) ^ g) << 2) + t]);
                unsigned a3 = __float_as_uint(sP[row1 * 64 + (((2 * s + 1) ^ g) << 2) + t]);
                const int r0 = (s * 8 + t) * 128;
                const int r1 = (s * 8 + t + 4) * 128;
                #pragma unroll
                for (int n = 0; n < 8; n++) {
                    int c4a = (16 * h + 2 * n + u) ^ (2 * t);
                    int c4b = (16 * h + 2 * n + u) ^ (2 * t + 8);
                    unsigned b0 = f2tf(sV[r0 + c4a * 4 + w]);
                    unsigned b1 = f2tf(sV[r1 + c4b * 4 + w]);
                    mma8(oAcc[n], a0, a1, a2, a3, b0, b1);
                }
            }

            __syncthreads();   // V buffer free; also covers P reads (PV done)

            // ---- issue V(kt+1) load ----
            if (kt + 1 < nkt) {
                int koff = (kt + 1) * BKT * 32;
                #pragma unroll
                for (int i = 0; i < 8; i++) {
                    int idx = tid + i * 256;
                    int row = idx >> 5;
                    int c4  = idx & 31;
                    int dV = row * 32 + (c4 ^ ((row & 7) << 1));
                    cpa16(kV_base + (uint32_t)dV * 16u, gV4 + koff + idx);
                }
                asm volatile("cp.async.commit_group;\n" ::: "memory");
            }
        }

        // ---- epilogue: cross-half row-sum exchange, normalize, store ----
        float rs0 = lacc0, rs1 = lacc1;
        rs0 += __shfl_xor_sync(0xffffffffu, rs0, 1);
        rs0 += __shfl_xor_sync(0xffffffffu, rs0, 2);
        rs1 += __shfl_xor_sync(0xffffffffu, rs1, 1);
        rs1 += __shfl_xor_sync(0xffffffffu, rs1, 2);
        if (t == 0) {
            sSum[h * 64 + row0] = rs0;
            sSum[h * 64 + row1] = rs1;
        }
        __syncthreads();
        float inv0 = 1.f / (sSum[row0] + sSum[64 + row0]);
        float inv1 = 1.f / (sSum[row1] + sSum[64 + row1]);

        float* gO = out + ((size_t)b * SEQ + q0) * HD;
        #pragma unroll
        for (int n = 0; n < 8; n++) {
            int col = h * 64 + n * 8 + 2 * t;
            *reinterpret_cast<float2*>(&gO[row0 * HD + col]) =
                make_float2(oAcc[n][0] * inv0, oAcc[n][1] * inv0);
            *reinterpret_cast<float2*>(&gO[row1 * HD + col]) =
                make_float2(oAcc[n][2] * inv1, oAcc[n][3] * inv1);
        }
        __syncthreads();   // sSum reads done before next item's sItem write/Q store
    }
}

extern "C" void kernel_launch(void* const* d_in, const int* in_sizes, int n_in,
                              void* d_out, int out_size) {
    const float* q  = (const float*)d_in[0];
    const float* k  = (const float*)d_in[1];
    const float* v  = (const float*)d_in[2];
    const int*   vl = (const int*)d_in[3];
    float* out = (float*)d_out;

    size_t smem_bytes = (size_t)SMEM_FLOATS * sizeof(float);   // 114688
    cudaFuncSetAttribute(fa_tf32_kernel, cudaFuncAttributeMaxDynamicSharedMemorySize, (int)smem_bytes);

    sched_kernel<<<1, 1>>>(vl);
    fa_tf32_kernel<<<304, 256, smem_bytes>>>(q, k, v, vl, out);
}

// round 15
// speedup vs baseline: 2.4114x; 1.1596x over previous
#include <cuda_runtime.h>
#include <cstdint>

// Flash attention, tf32 mma.sync (m16n8k8), fp32 accumulate.
// B=16, Q=2048, K=2048, D=128. Per-batch key masking via valid_lens.
// Round 15: retile S to 32x16/warp and PV to 32x32/warp so B-fragments are
// amortized across 2 m-tiles: -128 CVT and -64 LDS per warp-tile (~19% of
// issue slots) at identical register pressure. LPT queue, 2 CTAs/SM,
// per-use cvt.rna, no-max softmax, swizzled P, K(kt+1) overlaps PV.

static constexpr int BQ   = 64;
static constexpr int BKT  = 64;
static constexpr int HD   = 128;
static constexpr int SEQ  = 2048;
static constexpr int NB   = 16;
static constexpr int NITEMS = (SEQ / BQ) * NB;   // 512

// smem float offsets
static constexpr int Q_OFF = 0;        // 64x128 = 8192 floats
static constexpr int K_OFF = 8192;     // 64x128 = 8192
static constexpr int V_OFF = 16384;    // 64x128 = 8192
static constexpr int P_OFF = 24576;    // 64x64  = 4096 (XOR-swizzled; also scratch)
static constexpr int SMEM_FLOATS = P_OFF + 4096;   // 28672 -> 114688 B

__device__ int g_ctr;
__device__ int g_perm[NB];

// 1-thread scheduler: reset queue, sort batches by descending vlen (LPT).
__global__ void sched_kernel(const int* __restrict__ vlens) {
    g_ctr = 0;
    int vl[NB];
    bool used[NB];
    #pragma unroll
    for (int i = 0; i < NB; i++) { vl[i] = vlens[i]; used[i] = false; }
    for (int r = 0; r < NB; r++) {
        int best = -1, bi = 0;
        for (int i = 0; i < NB; i++)
            if (!used[i] && vl[i] > best) { best = vl[i]; bi = i; }
        used[bi] = true;
        g_perm[r] = bi;
    }
}

__device__ __forceinline__ unsigned f2tf(float x) {
    unsigned r;
    asm("cvt.rna.tf32.f32 %0, %1;" : "=r"(r) : "f"(x));
    return r;
}

__device__ __forceinline__ void mma8(float* c,
                                     unsigned a0, unsigned a1, unsigned a2, unsigned a3,
                                     unsigned b0, unsigned b1) {
    asm volatile(
        "mma.sync.aligned.m16n8k8.row.col.f32.tf32.tf32.f32 "
        "{%0,%1,%2,%3}, {%4,%5,%6,%7}, {%8,%9}, {%0,%1,%2,%3};\n"
        : "+f"(c[0]), "+f"(c[1]), "+f"(c[2]), "+f"(c[3])
        : "r"(a0), "r"(a1), "r"(a2), "r"(a3), "r"(b0), "r"(b1));
}

__device__ __forceinline__ void cpa16(uint32_t dst, const void* src) {
    asm volatile("cp.async.cg.shared.global [%0], [%1], 16;\n" :: "r"(dst), "l"(src));
}

extern __shared__ float smem[];

__global__ __launch_bounds__(256, 2)
void fa_tf32_kernel(const float* __restrict__ q,
                    const float* __restrict__ k,
                    const float* __restrict__ v,
                    const int*   __restrict__ vlens,
                    float*       __restrict__ out) {
    const int tid  = threadIdx.x;
    const int warp = tid >> 5;
    const int lane = tid & 31;
    const int g    = lane >> 2;
    const int t    = lane & 3;
    const int qh   = warp >> 2;        // 32-row q half (0..1)
    const int kq   = warp & 3;         // S: key quarter / PV: d quarter

    const float scale = 0.088388347648318447f;  // 1/sqrt(128)

    uint32_t smem_u32;
    asm("{ .reg .u64 tmp; cvta.to.shared.u64 tmp, %1; cvt.u32.u64 %0, tmp; }"
        : "=r"(smem_u32) : "l"(smem));

    const uint32_t kK_base = smem_u32 + (uint32_t)K_OFF * 4u;
    const uint32_t kV_base = smem_u32 + (uint32_t)V_OFF * 4u;

    const float* sQ = smem + Q_OFF;
    float*       sP = smem + P_OFF;
    float*       sSum = smem + P_OFF;                        // 256-float scratch
    int*         sItem = reinterpret_cast<int*>(smem + P_OFF + 300);

    const int rb0 = qh * 32 + g;       // m-tile 0 base row (rb0 & 7 == g)
    const int rb1 = rb0 + 16;          // m-tile 1 base row (rb1 & 7 == g)

    while (true) {
        if (tid == 0) *sItem = atomicAdd(&g_ctr, 1);
        __syncthreads();
        const int item = *sItem;
        if (item >= NITEMS) return;

        const int b  = g_perm[item >> 5];      // LPT: longest batches first
        const int q0 = (item & 31) * BQ;
        const int vlen = vlens[b];
        const int nkt  = (vlen + BKT - 1) >> 6;

        const float4* gQ4 = reinterpret_cast<const float4*>(q + ((size_t)b * SEQ + q0) * HD);
        const float4* gK4 = reinterpret_cast<const float4*>(k + (size_t)b * SEQ * HD);
        const float4* gV4 = reinterpret_cast<const float4*>(v + (size_t)b * SEQ * HD);

        // ---- prologue: issue K(0), V(0) loads ----
        #pragma unroll
        for (int i = 0; i < 8; i++) {
            int idx = tid + i * 256;       // 0..2047 float4
            int row = idx >> 5;
            int c4  = idx & 31;
            int dK = row * 32 + (c4 ^ (row & 7));
            int dV = row * 32 + (c4 ^ ((row & 7) << 1));
            cpa16(kK_base + (uint32_t)dK * 16u, gK4 + idx);
            cpa16(kV_base + (uint32_t)dV * 16u, gV4 + idx);
        }
        asm volatile("cp.async.commit_group;\n" ::: "memory");

        // ---- Q tile: scale + tf32 into swizzled smem (overlaps cp.async) ----
        {
            float* sQw = smem + Q_OFF;
            #pragma unroll
            for (int i = 0; i < 8; i++) {
                int idx = tid + i * 256;   // 0..2047 float4
                int row = idx >> 5;
                int c4  = idx & 31;
                float4 x = gQ4[idx];
                x.x = __uint_as_float(f2tf(x.x * scale));
                x.y = __uint_as_float(f2tf(x.y * scale));
                x.z = __uint_as_float(f2tf(x.z * scale));
                x.w = __uint_as_float(f2tf(x.w * scale));
                int d4 = row * 32 + (c4 ^ (row & 7));
                *reinterpret_cast<float4*>(&sQw[d4 * 4]) = x;
            }
        }

        float lacc[2][2] = {{0.f, 0.f}, {0.f, 0.f}};
        float oAcc[2][4][4];
        #pragma unroll
        for (int mt = 0; mt < 2; mt++)
            #pragma unroll
            for (int n = 0; n < 4; n++)
                #pragma unroll
                for (int e = 0; e < 4; e++) oAcc[mt][n][e] = 0.f;

        for (int kt = 0; kt < nkt; kt++) {
            const int kbase = kt * BKT;

            asm volatile("cp.async.wait_group 0;\n" ::: "memory");
            __syncthreads();

            const float* sK = smem + K_OFF;
            const float* sV = smem + V_OFF;

            // ---- S = Q @ K^T : 32 rows x 16 keys (quarter kq) per warp ----
            float sAcc[2][2][4];
            #pragma unroll
            for (int mt = 0; mt < 2; mt++)
                #pragma unroll
                for (int n = 0; n < 2; n++)
                    #pragma unroll
                    for (int e = 0; e < 4; e++) sAcc[mt][n][e] = 0.f;

            #pragma unroll
            for (int s = 0; s < 16; s++) {
                const int cA0 = ((2 * s)     ^ g) * 4 + t;
                const int cA1 = ((2 * s + 1) ^ g) * 4 + t;
                unsigned a[2][4];
                #pragma unroll
                for (int mt = 0; mt < 2; mt++) {
                    int rb = (mt == 0) ? rb0 : rb1;
                    a[mt][0] = __float_as_uint(sQ[rb * 128 + cA0]);
                    a[mt][1] = __float_as_uint(sQ[(rb + 8) * 128 + cA0]);
                    a[mt][2] = __float_as_uint(sQ[rb * 128 + cA1]);
                    a[mt][3] = __float_as_uint(sQ[(rb + 8) * 128 + cA1]);
                }
                #pragma unroll
                for (int n = 0; n < 2; n++) {
                    int key = kq * 16 + n * 8 + g;   // key & 7 == g
                    unsigned b0 = f2tf(sK[key * 128 + cA0]);
                    unsigned b1 = f2tf(sK[key * 128 + cA1]);
                    mma8(sAcc[0][n], a[0][0], a[0][1], a[0][2], a[0][3], b0, b1);
                    mma8(sAcc[1][n], a[1][0], a[1][1], a[1][2], a[1][3], b0, b1);
                }
            }

            // ---- exp (no max), mask, swizzled P store, row-sum partials ----
            const bool boundary = (kbase + BKT > vlen);
            const int sub = (t & 1) * 2;
            #pragma unroll
            for (int mt = 0; mt < 2; mt++) {
                int rlo = (mt == 0) ? rb0 : rb1;
                #pragma unroll
                for (int n = 0; n < 2; n++) {
                    float p0 = __expf(sAcc[mt][n][0]);
                    float p1 = __expf(sAcc[mt][n][1]);
                    float p2 = __expf(sAcc[mt][n][2]);
                    float p3 = __expf(sAcc[mt][n][3]);
                    if (boundary) {
                        int key = kbase + kq * 16 + n * 8 + 2 * t;
                        if (key     >= vlen) { p0 = 0.f; p2 = 0.f; }
                        if (key + 1 >= vlen) { p1 = 0.f; p3 = 0.f; }
                    }
                    lacc[mt][0] += p0 + p1;
                    lacc[mt][1] += p2 + p3;
                    int c4p = 4 * kq + 2 * n + (t >> 1);     // col>>2
                    int idx0 = rlo * 64 + ((c4p ^ g) << 2) + sub;
                    int idx1 = (rlo + 8) * 64 + ((c4p ^ g) << 2) + sub;
                    *reinterpret_cast<float2*>(&sP[idx0]) = make_float2(p0, p1);
                    *reinterpret_cast<float2*>(&sP[idx1]) = make_float2(p2, p3);
                }
            }

            __syncthreads();   // P ready; K buffer no longer needed

            // ---- overlap: prefetch K(kt+1) during PV ----
            if (kt + 1 < nkt) {
                int koff = (kt + 1) * BKT * 32;
                #pragma unroll
                for (int i = 0; i < 8; i++) {
                    int idx = tid + i * 256;
                    int row = idx >> 5;
                    int c4  = idx & 31;
                    int dK = row * 32 + (c4 ^ (row & 7));
                    cpa16(kK_base + (uint32_t)dK * 16u, gK4 + koff + idx);
                }
                asm volatile("cp.async.commit_group;\n" ::: "memory");
            }

            // ---- O += P @ V : 32 rows x 32 d-cols (quarter kq) per warp ----
            const int u = g >> 2;
            const int w = g & 3;
            #pragma unroll
            for (int s = 0; s < 8; s++) {
                unsigned aT[2][4];
                #pragma unroll
                for (int mt = 0; mt < 2; mt++) {
                    int rb = (mt == 0) ? rb0 : rb1;
                    aT[mt][0] = __float_as_uint(sP[rb * 64 + (((2 * s)     ^ g) << 2) + t]);
                    aT[mt][1] = __float_as_uint(sP[(rb + 8) * 64 + (((2 * s)     ^ g) << 2) + t]);
                    aT[mt][2] = __float_as_uint(sP[rb * 64 + (((2 * s + 1) ^ g) << 2) + t]);
                    aT[mt][3] = __float_as_uint(sP[(rb + 8) * 64 + (((2 * s + 1) ^ g) << 2) + t]);
                }
                const int r0 = (s * 8 + t) * 128;
                const int r1 = (s * 8 + t + 4) * 128;
                #pragma unroll
                for (int n = 0; n < 4; n++) {
                    int c4a = (8 * kq + 2 * n + u) ^ (2 * t);
                    int c4b = (8 * kq + 2 * n + u) ^ (2 * t + 8);
                    unsigned b0 = f2tf(sV[r0 + c4a * 4 + w]);
                    unsigned b1 = f2tf(sV[r1 + c4b * 4 + w]);
                    mma8(oAcc[0][n], aT[0][0], aT[0][1], aT[0][2], aT[0][3], b0, b1);
                    mma8(oAcc[1][n], aT[1][0], aT[1][1], aT[1][2], aT[1][3], b0, b1);
                }
            }

            __syncthreads();   // V buffer free; also covers P reads (PV done)

            // ---- issue V(kt+1) load ----
            if (kt + 1 < nkt) {
                int koff = (kt + 1) * BKT * 32;
                #pragma unroll
                for (int i = 0; i < 8; i++) {
                    int idx = tid + i * 256;
                    int row = idx >> 5;
                    int c4  = idx & 31;
                    int dV = row * 32 + (c4 ^ ((row & 7) << 1));
                    cpa16(kV_base + (uint32_t)dV * 16u, gV4 + koff + idx);
                }
                asm volatile("cp.async.commit_group;\n" ::: "memory");
            }
        }

        // ---- epilogue: 4-way row-sum partials, normalize, store ----
        #pragma unroll
        for (int mt = 0; mt < 2; mt++)
            #pragma unroll
            for (int rp = 0; rp < 2; rp++) {
                lacc[mt][rp] += __shfl_xor_sync(0xffffffffu, lacc[mt][rp], 1);
                lacc[mt][rp] += __shfl_xor_sync(0xffffffffu, lacc[mt][rp], 2);
            }
        if (t == 0) {
            sSum[kq * 64 + rb0]      = lacc[0][0];
            sSum[kq * 64 + rb0 + 8]  = lacc[0][1];
            sSum[kq * 64 + rb1]      = lacc[1][0];
            sSum[kq * 64 + rb1 + 8]  = lacc[1][1];
        }
        __syncthreads();

        float inv[2][2];
        #pragma unroll
        for (int mt = 0; mt < 2; mt++) {
            int rlo = (mt == 0) ? rb0 : rb1;
            inv[mt][0] = 1.f / (sSum[rlo] + sSum[64 + rlo] + sSum[128 + rlo] + sSum[192 + rlo]);
            inv[mt][1] = 1.f / (sSum[rlo + 8] + sSum[64 + rlo + 8] + sSum[128 + rlo + 8] + sSum[192 + rlo + 8]);
        }

        float* gO = out + ((size_t)b * SEQ + q0) * HD;
        #pragma unroll
        for (int mt = 0; mt < 2; mt++) {
            int rlo = (mt == 0) ? rb0 : rb1;
            #pragma unroll
            for (int n = 0; n < 4; n++) {
                int col = kq * 32 + n * 8 + 2 * t;
                *reinterpret_cast<float2*>(&gO[rlo * HD + col]) =
                    make_float2(oAcc[mt][n][0] * inv[mt][0], oAcc[mt][n][1] * inv[mt][0]);
                *reinterpret_cast<float2*>(&gO[(rlo + 8) * HD + col]) =
                    make_float2(oAcc[mt][n][2] * inv[mt][1], oAcc[mt][n][3] * inv[mt][1]);
            }
        }
        __syncthreads();   // sSum reads done before next item's writes
    }
}

extern "C" void kernel_launch(void* const* d_in, const int* in_sizes, int n_in,
                              void* d_out, int out_size) {
    const float* q  = (const float*)d_in[0];
    const float* k  = (const float*)d_in[1];
    const float* v  = (const float*)d_in[2];
    const int*   vl = (const int*)d_in[3];
    float* out = (float*)d_out;

    size_t smem_bytes = (size_t)SMEM_FLOATS * sizeof(float);   // 114688
    cudaFuncSetAttribute(fa_tf32_kernel, cudaFuncAttributeMaxDynamicSharedMemorySize, (int)smem_bytes);

    sched_kernel<<<1, 1>>>(vl);
    fa_tf32_kernel<<<304, 256, smem_bytes>>>(q, k, v, vl, out);
}